// round 1
// baseline (speedup 1.0000x reference)
#include <cuda_runtime.h>
#include <cuda_bf16.h>

// ---------------------------------------------------------------------------
// GCN 4-layer forward on GB300.
// Strategy: build CSR-by-dst once per call (degrees -> scan -> scatter), then
// each layer = [dense GEMM with fused norm_out scale] + [gather-aggregate with
// fused norm_in/bias/relu]. Node feature matrices (<=51MB) are L2-friendly.
// ---------------------------------------------------------------------------

#define MAX_N 100000
#define MAX_E 800000
#define MAX_G 500

__device__ float g_norm_out[MAX_N];
__device__ float g_norm_in[MAX_N];
__device__ int   g_deg_out[MAX_N];
__device__ int   g_deg_in[MAX_N];
__device__ int   g_row_ptr[MAX_N + 1];
__device__ int   g_cursor[MAX_N];
__device__ int   g_csr_src[MAX_E];
__device__ float g_h0[MAX_N * 128];
__device__ float g_h1[MAX_N * 128];
__device__ float g_gsum[MAX_G * 4];
__device__ int   g_gcnt[MAX_G];

// ---------------------------------------------------------------------------
__global__ void zero_kernel(int n, int g) {
    int i = blockIdx.x * blockDim.x + threadIdx.x;
    if (i < n) { g_deg_out[i] = 0; g_deg_in[i] = 0; }
    if (i < g * 4) g_gsum[i] = 0.0f;
    if (i < g) g_gcnt[i] = 0;
}

__global__ void degree_kernel(const int* __restrict__ src,
                              const int* __restrict__ dst, int e) {
    int i = blockIdx.x * blockDim.x + threadIdx.x;
    if (i < e) {
        atomicAdd(&g_deg_out[src[i]], 1);
        atomicAdd(&g_deg_in[dst[i]], 1);
    }
}

__global__ void norm_kernel(int n) {
    int i = blockIdx.x * blockDim.x + threadIdx.x;
    if (i < n) {
        g_norm_out[i] = rsqrtf(fmaxf((float)g_deg_out[i], 1.0f));
        g_norm_in[i]  = rsqrtf(fmaxf((float)g_deg_in[i], 1.0f));
    }
}

// Exclusive scan of g_deg_in into g_row_ptr / g_cursor. One block, 1024 thr.
__global__ void scan_kernel(int n) {
    __shared__ int s_warp[32];
    __shared__ int s_carry;
    int tid = threadIdx.x, lane = tid & 31, wid = tid >> 5;
    if (tid == 0) s_carry = 0;
    __syncthreads();
    for (int base = 0; base < n; base += 1024) {
        int i = base + tid;
        int v = (i < n) ? g_deg_in[i] : 0;
        int s = v;
        #pragma unroll
        for (int o = 1; o < 32; o <<= 1) {
            int t = __shfl_up_sync(0xffffffffu, s, o);
            if (lane >= o) s += t;
        }
        if (lane == 31) s_warp[wid] = s;
        __syncthreads();
        if (wid == 0) {
            int ws = s_warp[lane];
            #pragma unroll
            for (int o = 1; o < 32; o <<= 1) {
                int t = __shfl_up_sync(0xffffffffu, ws, o);
                if (lane >= o) ws += t;
            }
            s_warp[lane] = ws;
        }
        __syncthreads();
        int prefix = (wid > 0) ? s_warp[wid - 1] : 0;
        int incl = s + prefix;
        int excl = s_carry + incl - v;
        if (i < n) { g_row_ptr[i] = excl; g_cursor[i] = excl; }
        __syncthreads();
        if (tid == 1023) s_carry += s_warp[31];
        __syncthreads();
    }
    if (tid == 0) g_row_ptr[n] = s_carry;
}

__global__ void csr_fill_kernel(const int* __restrict__ src,
                                const int* __restrict__ dst, int e) {
    int i = blockIdx.x * blockDim.x + threadIdx.x;
    if (i < e) {
        int p = atomicAdd(&g_cursor[dst[i]], 1);
        g_csr_src[p] = src[i];
    }
}

// h0[i,:] = x[i,:] * norm_out[i]   (64 floats/row = 16 float4)
__global__ void scale_x_kernel(const float* __restrict__ x, int n) {
    int i = blockIdx.x * blockDim.x + threadIdx.x;
    if (i < n * 16) {
        int row = i >> 4;
        float s = g_norm_out[row];
        float4 v = ((const float4*)x)[i];
        v.x *= s; v.y *= s; v.z *= s; v.w *= s;
        ((float4*)g_h0)[i] = v;
    }
}

// ---------------------------------------------------------------------------
// Gather-aggregate: out[n,:] = relu?( norm_in[n] * sum_{e in CSR(n)} in[src_e,:] + bias )
// DIM=64: warp/node, 2 floats/lane (float2). DIM=32: warp/node, 1 float/lane.
// DIM=4: 8 nodes/warp, 4 lanes/node.
// ---------------------------------------------------------------------------
template<int DIM, bool RELU, bool HASB>
__global__ void agg_kernel(const float* __restrict__ hin,
                           float* __restrict__ hout,
                           const float* __restrict__ bias, int n) {
    constexpr int LPN = (DIM >= 32) ? 32 : DIM;   // lanes per node
    constexpr int NPW = 32 / LPN;                 // nodes per warp
    int warp = (blockIdx.x * blockDim.x + threadIdx.x) >> 5;
    int lane = threadIdx.x & 31;
    int node = warp * NPW + (lane / LPN);
    int l = lane % LPN;
    if (node >= n) return;
    int beg = g_row_ptr[node];
    int end = g_row_ptr[node + 1];
    float ni = g_norm_in[node];
    if (DIM == 64) {
        float ax = 0.0f, ay = 0.0f;
        for (int e = beg; e < end; e++) {
            int s = g_csr_src[e];
            float2 v = *(const float2*)&hin[s * 64 + l * 2];
            ax += v.x; ay += v.y;
        }
        ax *= ni; ay *= ni;
        if (HASB) { ax += bias[l * 2]; ay += bias[l * 2 + 1]; }
        if (RELU) { ax = fmaxf(ax, 0.0f); ay = fmaxf(ay, 0.0f); }
        float2 o; o.x = ax; o.y = ay;
        *(float2*)&hout[node * 64 + l * 2] = o;
    } else {
        float a = 0.0f;
        for (int e = beg; e < end; e++) {
            int s = g_csr_src[e];
            a += hin[s * DIM + l];
        }
        a *= ni;
        if (HASB) a += bias[l];
        if (RELU) a = fmaxf(a, 0.0f);
        hout[node * DIM + l] = a;
    }
}

// ---------------------------------------------------------------------------
// Dense: out[N,M] = op( in[N,K] @ W[K,M] ),  op = (+bias)(*rowscale)(relu)
// Shared: transposed W (float4 along K per column) + input row tile.
// Each thread: fixed column, RPT rows register-blocked (reuses w float4).
// ---------------------------------------------------------------------------
template<int K, int M, bool RELU>
__global__ void gemm_kernel(const float* __restrict__ in,
                            const float* __restrict__ W,
                            const float* __restrict__ bias,
                            const float* __restrict__ rowscale,
                            float* __restrict__ out, int n) {
    constexpr int THREADS = 256;
    constexpr int RPAR = THREADS / M;
    constexpr int RPT = 4;
    constexpr int RTILE = RPAR * RPT;
    __shared__ float sW[K * M];        // sW[col*K + k]
    __shared__ float sIn[RTILE * K];

    for (int idx = threadIdx.x; idx < K * M; idx += THREADS) {
        int k = idx / M, c = idx % M;
        sW[c * K + k] = W[idx];
    }
    __syncthreads();

    int col = threadIdx.x % M;
    int rg  = threadIdx.x / M;
    const float4* wt = (const float4*)&sW[col * K];

    int ntiles = (n + RTILE - 1) / RTILE;
    for (int t = blockIdx.x; t < ntiles; t += gridDim.x) {
        int row0 = t * RTILE;
        int rows = min(RTILE, n - row0);
        __syncthreads();
        {
            const float4* gin = (const float4*)&in[(long)row0 * K];
            float4* s4 = (float4*)sIn;
            int nv = rows * K / 4;
            for (int idx = threadIdx.x; idx < nv; idx += THREADS)
                s4[idx] = gin[idx];
        }
        __syncthreads();
        float acc[RPT];
        #pragma unroll
        for (int r = 0; r < RPT; r++) acc[r] = 0.0f;
        #pragma unroll
        for (int k4 = 0; k4 < K / 4; k4++) {
            float4 w = wt[k4];
            #pragma unroll
            for (int r = 0; r < RPT; r++) {
                int rr = rg + r * RPAR;
                float4 x = *(const float4*)&sIn[rr * K + k4 * 4];
                acc[r] = fmaf(w.x, x.x,
                         fmaf(w.y, x.y,
                         fmaf(w.z, x.z,
                         fmaf(w.w, x.w, acc[r]))));
            }
        }
        #pragma unroll
        for (int r = 0; r < RPT; r++) {
            int rr = rg + r * RPAR;
            if (rr < rows) {
                int row = row0 + rr;
                float v = acc[r];
                if (bias) v += bias[col];
                if (rowscale) v *= rowscale[row];
                if (RELU) v = fmaxf(v, 0.0f);
                out[(long)row * M + col] = v;
            }
        }
    }
}

// ---------------------------------------------------------------------------
__global__ void graph_sum_kernel(const float* __restrict__ h,
                                 const int* __restrict__ gid, int n) {
    int i = blockIdx.x * blockDim.x + threadIdx.x;
    if (i < n) {
        int g = gid[i];
        float4 v = *(const float4*)&h[i * 4];
        atomicAdd(&g_gsum[g * 4 + 0], v.x);
        atomicAdd(&g_gsum[g * 4 + 1], v.y);
        atomicAdd(&g_gsum[g * 4 + 2], v.z);
        atomicAdd(&g_gsum[g * 4 + 3], v.w);
        atomicAdd(&g_gcnt[g], 1);
    }
}

__global__ void graph_mean_kernel(float* __restrict__ out, int g) {
    int i = blockIdx.x * blockDim.x + threadIdx.x;
    if (i < g * 4) {
        float c = fmaxf((float)g_gcnt[i >> 2], 1.0f);
        out[i] = g_gsum[i] / c;
    }
}

// ---------------------------------------------------------------------------
extern "C" void kernel_launch(void* const* d_in, const int* in_sizes, int n_in,
                              void* d_out, int out_size) {
    const float* x  = (const float*)d_in[0];
    const float* W1 = (const float*)d_in[1];
    const float* b1 = (const float*)d_in[2];
    const float* W2 = (const float*)d_in[3];
    const float* b2 = (const float*)d_in[4];
    const float* W3 = (const float*)d_in[5];
    const float* b3 = (const float*)d_in[6];
    const float* W4 = (const float*)d_in[7];
    const float* b4 = (const float*)d_in[8];
    const int* src = (const int*)d_in[9];
    const int* dst = (const int*)d_in[10];
    const int* gid = (const int*)d_in[11];
    float* out = (float*)d_out;

    int n = in_sizes[0] / 64;   // nodes
    int e = in_sizes[9];        // edges
    int g = out_size / 4;       // graphs

    float *h0, *h1, *nrm_out;
    cudaGetSymbolAddress((void**)&h0, g_h0);
    cudaGetSymbolAddress((void**)&h1, g_h1);
    cudaGetSymbolAddress((void**)&nrm_out, g_norm_out);

    const int T = 256;
    auto blocks = [](int work, int t) { return (work + t - 1) / t; };
    auto agg_grid = [&](int npw) {       // blocks for agg kernels
        int warps = (n + npw - 1) / npw;
        return (warps * 32 + T - 1) / T;
    };

    // Graph preprocessing
    zero_kernel<<<blocks(n, T), T>>>(n, g);
    degree_kernel<<<blocks(e, T), T>>>(src, dst, e);
    norm_kernel<<<blocks(n, T), T>>>(n);
    scan_kernel<<<1, 1024>>>(n);
    csr_fill_kernel<<<blocks(e, T), T>>>(src, dst, e);

    const int GEMM_GRID = 1184;  // 148 SMs * 8

    // Layer 1: agg(x * norm_out) -> (* norm_in) -> @W1 + b1 -> relu
    scale_x_kernel<<<blocks(n * 16, T), T>>>(x, n);
    agg_kernel<64, false, false><<<agg_grid(1), T>>>(h0, h1, nullptr, n);
    gemm_kernel<64, 128, true><<<GEMM_GRID, T>>>(h1, W1, b1, nullptr, h0, n);

    // Layer 2: (h @ W2) * norm_out -> agg -> * norm_in + b2 -> relu
    gemm_kernel<128, 64, false><<<GEMM_GRID, T>>>(h0, W2, nullptr, nrm_out, h1, n);
    agg_kernel<64, true, true><<<agg_grid(1), T>>>(h1, h0, b2, n);

    // Layer 3
    gemm_kernel<64, 32, false><<<GEMM_GRID, T>>>(h0, W3, nullptr, nrm_out, h1, n);
    agg_kernel<32, true, true><<<agg_grid(1), T>>>(h1, h0, b3, n);

    // Layer 4 (no relu)
    gemm_kernel<32, 4, false><<<GEMM_GRID, T>>>(h0, W4, nullptr, nrm_out, h1, n);
    agg_kernel<4, false, true><<<agg_grid(8), T>>>(h1, h0, b4, n);

    // Per-graph mean readout
    graph_sum_kernel<<<blocks(n, T), T>>>(h0, gid, n);
    graph_mean_kernel<<<blocks(g * 4, T), T>>>(out, g);
}

// round 2
// speedup vs baseline: 1.0026x; 1.0026x over previous
#include <cuda_runtime.h>
#include <cuda_bf16.h>

// ---------------------------------------------------------------------------
// GCN 4-layer forward on GB300.
// Strategy: build CSR-by-dst once per call (degrees -> scan -> scatter), then
// each layer = [dense GEMM with fused norm_out scale] + [gather-aggregate with
// fused norm_in/bias/relu]. Node feature matrices (<=51MB) are L2-friendly.
// ---------------------------------------------------------------------------

#define MAX_N 100000
#define MAX_E 800000
#define MAX_G 500

__device__ float g_norm_out[MAX_N];
__device__ float g_norm_in[MAX_N];
__device__ int   g_deg_out[MAX_N];
__device__ int   g_deg_in[MAX_N];
__device__ int   g_row_ptr[MAX_N + 1];
__device__ int   g_cursor[MAX_N];
__device__ int   g_csr_src[MAX_E];
__device__ float g_h0[MAX_N * 128];
__device__ float g_h1[MAX_N * 128];
__device__ float g_gsum[MAX_G * 4];
__device__ int   g_gcnt[MAX_G];

// ---------------------------------------------------------------------------
__global__ void zero_kernel(int n, int g) {
    int i = blockIdx.x * blockDim.x + threadIdx.x;
    if (i < n) { g_deg_out[i] = 0; g_deg_in[i] = 0; }
    if (i < g * 4) g_gsum[i] = 0.0f;
    if (i < g) g_gcnt[i] = 0;
}

__global__ void degree_kernel(const int* __restrict__ src,
                              const int* __restrict__ dst, int e) {
    int i = blockIdx.x * blockDim.x + threadIdx.x;
    if (i < e) {
        atomicAdd(&g_deg_out[src[i]], 1);
        atomicAdd(&g_deg_in[dst[i]], 1);
    }
}

__global__ void norm_kernel(int n) {
    int i = blockIdx.x * blockDim.x + threadIdx.x;
    if (i < n) {
        g_norm_out[i] = rsqrtf(fmaxf((float)g_deg_out[i], 1.0f));
        g_norm_in[i]  = rsqrtf(fmaxf((float)g_deg_in[i], 1.0f));
    }
}

// Exclusive scan of g_deg_in into g_row_ptr / g_cursor. One block, 1024 thr.
__global__ void scan_kernel(int n) {
    __shared__ int s_warp[32];
    __shared__ int s_carry;
    int tid = threadIdx.x, lane = tid & 31, wid = tid >> 5;
    if (tid == 0) s_carry = 0;
    __syncthreads();
    for (int base = 0; base < n; base += 1024) {
        int i = base + tid;
        int v = (i < n) ? g_deg_in[i] : 0;
        int s = v;
        #pragma unroll
        for (int o = 1; o < 32; o <<= 1) {
            int t = __shfl_up_sync(0xffffffffu, s, o);
            if (lane >= o) s += t;
        }
        if (lane == 31) s_warp[wid] = s;
        __syncthreads();
        if (wid == 0) {
            int ws = s_warp[lane];
            #pragma unroll
            for (int o = 1; o < 32; o <<= 1) {
                int t = __shfl_up_sync(0xffffffffu, ws, o);
                if (lane >= o) ws += t;
            }
            s_warp[lane] = ws;
        }
        __syncthreads();
        int prefix = (wid > 0) ? s_warp[wid - 1] : 0;
        int incl = s + prefix;
        int excl = s_carry + incl - v;
        if (i < n) { g_row_ptr[i] = excl; g_cursor[i] = excl; }
        __syncthreads();
        if (tid == 1023) s_carry += s_warp[31];
        __syncthreads();
    }
    if (tid == 0) g_row_ptr[n] = s_carry;
}

__global__ void csr_fill_kernel(const int* __restrict__ src,
                                const int* __restrict__ dst, int e) {
    int i = blockIdx.x * blockDim.x + threadIdx.x;
    if (i < e) {
        int p = atomicAdd(&g_cursor[dst[i]], 1);
        g_csr_src[p] = src[i];
    }
}

// h0[i,:] = x[i,:] * norm_out[i]   (64 floats/row = 16 float4)
__global__ void scale_x_kernel(const float* __restrict__ x, int n) {
    int i = blockIdx.x * blockDim.x + threadIdx.x;
    if (i < n * 16) {
        int row = i >> 4;
        float s = g_norm_out[row];
        float4 v = ((const float4*)x)[i];
        v.x *= s; v.y *= s; v.z *= s; v.w *= s;
        ((float4*)g_h0)[i] = v;
    }
}

// ---------------------------------------------------------------------------
// Gather-aggregate: out[n,:] = relu?( norm_in[n] * sum_{e in CSR(n)} in[src_e,:] + bias )
// DIM=64: warp/node, 2 floats/lane (float2). DIM=32: warp/node, 1 float/lane.
// DIM=4: 8 nodes/warp, 4 lanes/node.
// ---------------------------------------------------------------------------
template<int DIM, bool RELU, bool HASB>
__global__ void agg_kernel(const float* __restrict__ hin,
                           float* __restrict__ hout,
                           const float* __restrict__ bias, int n) {
    constexpr int LPN = (DIM >= 32) ? 32 : DIM;   // lanes per node
    constexpr int NPW = 32 / LPN;                 // nodes per warp
    int warp = (blockIdx.x * blockDim.x + threadIdx.x) >> 5;
    int lane = threadIdx.x & 31;
    int node = warp * NPW + (lane / LPN);
    int l = lane % LPN;
    if (node >= n) return;
    int beg = g_row_ptr[node];
    int end = g_row_ptr[node + 1];
    float ni = g_norm_in[node];
    if (DIM == 64) {
        float ax = 0.0f, ay = 0.0f;
        for (int e = beg; e < end; e++) {
            int s = g_csr_src[e];
            float2 v = *(const float2*)&hin[s * 64 + l * 2];
            ax += v.x; ay += v.y;
        }
        ax *= ni; ay *= ni;
        if (HASB) { ax += bias[l * 2]; ay += bias[l * 2 + 1]; }
        if (RELU) { ax = fmaxf(ax, 0.0f); ay = fmaxf(ay, 0.0f); }
        float2 o; o.x = ax; o.y = ay;
        *(float2*)&hout[node * 64 + l * 2] = o;
    } else {
        float a = 0.0f;
        for (int e = beg; e < end; e++) {
            int s = g_csr_src[e];
            a += hin[s * DIM + l];
        }
        a *= ni;
        if (HASB) a += bias[l];
        if (RELU) a = fmaxf(a, 0.0f);
        hout[node * DIM + l] = a;
    }
}

// ---------------------------------------------------------------------------
// Dense: out[N,M] = op( in[N,K] @ W[K,M] ),  op = (+bias)(*rowscale)(relu)
// Shared: transposed W (float4 along K per column) + input row tile.
// Each thread: fixed column, RPT rows register-blocked (reuses w float4).
// ---------------------------------------------------------------------------
template<int K, int M, bool RELU>
__global__ void gemm_kernel(const float* __restrict__ in,
                            const float* __restrict__ W,
                            const float* __restrict__ bias,
                            const float* __restrict__ rowscale,
                            float* __restrict__ out, int n) {
    constexpr int THREADS = 256;
    constexpr int RPAR = THREADS / M;
    constexpr int RPT = 4;
    constexpr int RTILE = RPAR * RPT;
    __shared__ float sW[K * M];        // sW[col*K + k]
    __shared__ float sIn[RTILE * K];

    for (int idx = threadIdx.x; idx < K * M; idx += THREADS) {
        int k = idx / M, c = idx % M;
        sW[c * K + k] = W[idx];
    }
    __syncthreads();

    int col = threadIdx.x % M;
    int rg  = threadIdx.x / M;
    const float4* wt = (const float4*)&sW[col * K];

    int ntiles = (n + RTILE - 1) / RTILE;
    for (int t = blockIdx.x; t < ntiles; t += gridDim.x) {
        int row0 = t * RTILE;
        int rows = min(RTILE, n - row0);
        __syncthreads();
        {
            const float4* gin = (const float4*)&in[(long)row0 * K];
            float4* s4 = (float4*)sIn;
            int nv = rows * K / 4;
            for (int idx = threadIdx.x; idx < nv; idx += THREADS)
                s4[idx] = gin[idx];
        }
        __syncthreads();
        float acc[RPT];
        #pragma unroll
        for (int r = 0; r < RPT; r++) acc[r] = 0.0f;
        #pragma unroll
        for (int k4 = 0; k4 < K / 4; k4++) {
            float4 w = wt[k4];
            #pragma unroll
            for (int r = 0; r < RPT; r++) {
                int rr = rg + r * RPAR;
                float4 x = *(const float4*)&sIn[rr * K + k4 * 4];
                acc[r] = fmaf(w.x, x.x,
                         fmaf(w.y, x.y,
                         fmaf(w.z, x.z,
                         fmaf(w.w, x.w, acc[r]))));
            }
        }
        #pragma unroll
        for (int r = 0; r < RPT; r++) {
            int rr = rg + r * RPAR;
            if (rr < rows) {
                int row = row0 + rr;
                float v = acc[r];
                if (bias) v += bias[col];
                if (rowscale) v *= rowscale[row];
                if (RELU) v = fmaxf(v, 0.0f);
                out[(long)row * M + col] = v;
            }
        }
    }
}

// ---------------------------------------------------------------------------
__global__ void graph_sum_kernel(const float* __restrict__ h,
                                 const int* __restrict__ gid, int n) {
    int i = blockIdx.x * blockDim.x + threadIdx.x;
    if (i < n) {
        int g = gid[i];
        float4 v = *(const float4*)&h[i * 4];
        atomicAdd(&g_gsum[g * 4 + 0], v.x);
        atomicAdd(&g_gsum[g * 4 + 1], v.y);
        atomicAdd(&g_gsum[g * 4 + 2], v.z);
        atomicAdd(&g_gsum[g * 4 + 3], v.w);
        atomicAdd(&g_gcnt[g], 1);
    }
}

__global__ void graph_mean_kernel(float* __restrict__ out, int g) {
    int i = blockIdx.x * blockDim.x + threadIdx.x;
    if (i < g * 4) {
        float c = fmaxf((float)g_gcnt[i >> 2], 1.0f);
        out[i] = g_gsum[i] / c;
    }
}

// ---------------------------------------------------------------------------
extern "C" void kernel_launch(void* const* d_in, const int* in_sizes, int n_in,
                              void* d_out, int out_size) {
    const float* x  = (const float*)d_in[0];
    const float* W1 = (const float*)d_in[1];
    const float* b1 = (const float*)d_in[2];
    const float* W2 = (const float*)d_in[3];
    const float* b2 = (const float*)d_in[4];
    const float* W3 = (const float*)d_in[5];
    const float* b3 = (const float*)d_in[6];
    const float* W4 = (const float*)d_in[7];
    const float* b4 = (const float*)d_in[8];
    const int* src = (const int*)d_in[9];
    const int* dst = (const int*)d_in[10];
    const int* gid = (const int*)d_in[11];
    float* out = (float*)d_out;

    int n = in_sizes[0] / 64;   // nodes
    int e = in_sizes[9];        // edges
    int g = out_size / 4;       // graphs

    float *h0, *h1, *nrm_out;
    cudaGetSymbolAddress((void**)&h0, g_h0);
    cudaGetSymbolAddress((void**)&h1, g_h1);
    cudaGetSymbolAddress((void**)&nrm_out, g_norm_out);

    const int T = 256;
    auto blocks = [](int work, int t) { return (work + t - 1) / t; };
    auto agg_grid = [&](int npw) {       // blocks for agg kernels
        int warps = (n + npw - 1) / npw;
        return (warps * 32 + T - 1) / T;
    };

    // Graph preprocessing
    zero_kernel<<<blocks(n, T), T>>>(n, g);
    degree_kernel<<<blocks(e, T), T>>>(src, dst, e);
    norm_kernel<<<blocks(n, T), T>>>(n);
    scan_kernel<<<1, 1024>>>(n);
    csr_fill_kernel<<<blocks(e, T), T>>>(src, dst, e);

    const int GEMM_GRID = 1184;  // 148 SMs * 8

    // Layer 1: agg(x * norm_out) -> (* norm_in) -> @W1 + b1 -> relu
    scale_x_kernel<<<blocks(n * 16, T), T>>>(x, n);
    agg_kernel<64, false, false><<<agg_grid(1), T>>>(h0, h1, nullptr, n);
    gemm_kernel<64, 128, true><<<GEMM_GRID, T>>>(h1, W1, b1, nullptr, h0, n);

    // Layer 2: (h @ W2) * norm_out -> agg -> * norm_in + b2 -> relu
    gemm_kernel<128, 64, false><<<GEMM_GRID, T>>>(h0, W2, nullptr, nrm_out, h1, n);
    agg_kernel<64, true, true><<<agg_grid(1), T>>>(h1, h0, b2, n);

    // Layer 3
    gemm_kernel<64, 32, false><<<GEMM_GRID, T>>>(h0, W3, nullptr, nrm_out, h1, n);
    agg_kernel<32, true, true><<<agg_grid(1), T>>>(h1, h0, b3, n);

    // Layer 4 (no relu)
    gemm_kernel<32, 4, false><<<GEMM_GRID, T>>>(h0, W4, nullptr, nrm_out, h1, n);
    agg_kernel<4, false, true><<<agg_grid(8), T>>>(h1, h0, b4, n);

    // Per-graph mean readout
    graph_sum_kernel<<<blocks(n, T), T>>>(h0, gid, n);
    graph_mean_kernel<<<blocks(g * 4, T), T>>>(out, g);
}

// round 3
// speedup vs baseline: 2.8414x; 2.8340x over previous
#include <cuda_runtime.h>

// ---------------------------------------------------------------------------
// GCN 4-layer forward on GB300 (sm_103a).
// R2: parallel scan, f32x2 register-tiled GEMMs (4 col x 8 row / thread),
// MLP-unrolled CSR gather aggregation, warp-reduced graph readout.
// ---------------------------------------------------------------------------

#define MAX_N 100000
#define MAX_E 800000
#define MAX_G 500

__device__ float g_norm_out[MAX_N];
__device__ float g_norm_in[MAX_N];
__device__ int   g_deg_out[MAX_N];
__device__ int   g_deg_in[MAX_N];
__device__ int   g_row_ptr[MAX_N + 1];
__device__ int   g_cursor[MAX_N];
__device__ int   g_csr_src[MAX_E];
__device__ float g_h0[MAX_N * 128];
__device__ float g_h1[MAX_N * 128];
__device__ float g_gsum[MAX_G * 4];
__device__ int   g_gcnt[MAX_G];
__device__ int   g_bsum[128];
__device__ int   g_boff[128];

typedef unsigned long long ull;

// ---- packed f32x2 helpers --------------------------------------------------
__device__ __forceinline__ ull pk(float lo, float hi) {
    ull r; asm("mov.b64 %0, {%1,%2};" : "=l"(r) : "f"(lo), "f"(hi)); return r;
}
__device__ __forceinline__ void fma2(ull& d, ull a, ull b) {
    asm("fma.rn.f32x2 %0, %1, %2, %0;" : "+l"(d) : "l"(a), "l"(b));
}
__device__ __forceinline__ float2 upk(ull v) {
    float2 f; asm("mov.b64 {%0,%1}, %2;" : "=f"(f.x), "=f"(f.y) : "l"(v)); return f;
}

// ---------------------------------------------------------------------------
__global__ void zero_kernel(int n, int g) {
    int i = blockIdx.x * blockDim.x + threadIdx.x;
    if (i < n) { g_deg_out[i] = 0; g_deg_in[i] = 0; }
    if (i < g * 4) g_gsum[i] = 0.0f;
    if (i < g) g_gcnt[i] = 0;
}

__global__ void degree_kernel(const int* __restrict__ src,
                              const int* __restrict__ dst, int e) {
    int i = blockIdx.x * blockDim.x + threadIdx.x;
    if (i < e) {
        atomicAdd(&g_deg_out[src[i]], 1);
        atomicAdd(&g_deg_in[dst[i]], 1);
    }
}

__global__ void norm_kernel(int n) {
    int i = blockIdx.x * blockDim.x + threadIdx.x;
    if (i < n) {
        g_norm_out[i] = rsqrtf(fmaxf((float)g_deg_out[i], 1.0f));
        g_norm_in[i]  = rsqrtf(fmaxf((float)g_deg_in[i], 1.0f));
    }
}

// ---- 3-pass parallel exclusive scan of deg_in -------------------------------
// pass1: per-block (1024 elems) sums.  pass2: scan block sums (1 block).
// pass3: per-block local scan + offset -> row_ptr/cursor.
__global__ void scan_pass1(int n) {
    __shared__ int sw[8];
    int b = blockIdx.x, t = threadIdx.x;
    int i0 = b * 1024 + t * 4;
    int s = 0;
    if (i0 + 3 < n) {
        int4 v = *(const int4*)&g_deg_in[i0];
        s = v.x + v.y + v.z + v.w;
    } else {
        for (int j = 0; j < 4; j++) if (i0 + j < n) s += g_deg_in[i0 + j];
    }
    #pragma unroll
    for (int o = 16; o; o >>= 1) s += __shfl_down_sync(0xffffffffu, s, o);
    if ((t & 31) == 0) sw[t >> 5] = s;
    __syncthreads();
    if (t < 8) {
        s = sw[t];
        #pragma unroll
        for (int o = 4; o; o >>= 1) s += __shfl_down_sync(0xffu, s, o);
        if (t == 0) g_bsum[b] = s;
    }
}

__global__ void scan_pass2(int nb, int n) {
    __shared__ int sw[4];
    int t = threadIdx.x, lane = t & 31, w = t >> 5;
    int v = (t < nb) ? g_bsum[t] : 0;
    int s = v;
    #pragma unroll
    for (int o = 1; o < 32; o <<= 1) {
        int x = __shfl_up_sync(0xffffffffu, s, o);
        if (lane >= o) s += x;
    }
    if (lane == 31) sw[w] = s;
    __syncthreads();
    int pre = 0;
    for (int j = 0; j < w; j++) pre += sw[j];
    int incl = s + pre;
    if (t < nb) g_boff[t] = incl - v;
    if (t == nb - 1) g_row_ptr[n] = incl;
}

__global__ void scan_pass3(int n) {
    __shared__ int swarp[8];
    int b = blockIdx.x, t = threadIdx.x, lane = t & 31, w = t >> 5;
    int i0 = b * 1024 + t * 4;
    int4 v = make_int4(0, 0, 0, 0);
    if (i0 + 3 < n) v = *(const int4*)&g_deg_in[i0];
    else {
        if (i0     < n) v.x = g_deg_in[i0];
        if (i0 + 1 < n) v.y = g_deg_in[i0 + 1];
        if (i0 + 2 < n) v.z = g_deg_in[i0 + 2];
        if (i0 + 3 < n) v.w = g_deg_in[i0 + 3];
    }
    int ts = v.x + v.y + v.z + v.w;
    int s = ts;
    #pragma unroll
    for (int o = 1; o < 32; o <<= 1) {
        int x = __shfl_up_sync(0xffffffffu, s, o);
        if (lane >= o) s += x;
    }
    if (lane == 31) swarp[w] = s;
    __syncthreads();
    if (w == 0 && lane < 8) {
        int ws = swarp[lane];
        #pragma unroll
        for (int o = 1; o < 8; o <<= 1) {
            int x = __shfl_up_sync(0xffu, ws, o);
            if (lane >= o) ws += x;
        }
        swarp[lane] = ws;
    }
    __syncthreads();
    int pre = (w > 0) ? swarp[w - 1] : 0;
    int e0 = g_boff[b] + pre + s - ts;
    int e1 = e0 + v.x, e2 = e1 + v.y, e3 = e2 + v.z;
    if (i0     < n) { g_row_ptr[i0]     = e0; g_cursor[i0]     = e0; }
    if (i0 + 1 < n) { g_row_ptr[i0 + 1] = e1; g_cursor[i0 + 1] = e1; }
    if (i0 + 2 < n) { g_row_ptr[i0 + 2] = e2; g_cursor[i0 + 2] = e2; }
    if (i0 + 3 < n) { g_row_ptr[i0 + 3] = e3; g_cursor[i0 + 3] = e3; }
}

__global__ void csr_fill_kernel(const int* __restrict__ src,
                                const int* __restrict__ dst, int e) {
    int i = blockIdx.x * blockDim.x + threadIdx.x;
    if (i < e) {
        int p = atomicAdd(&g_cursor[dst[i]], 1);
        g_csr_src[p] = src[i];
    }
}

// h0[i,:] = x[i,:] * norm_out[i]
__global__ void scale_x_kernel(const float* __restrict__ x, int n) {
    int i = blockIdx.x * blockDim.x + threadIdx.x;
    if (i < n * 16) {
        int row = i >> 4;
        float s = g_norm_out[row];
        float4 v = ((const float4*)x)[i];
        v.x *= s; v.y *= s; v.z *= s; v.w *= s;
        ((float4*)g_h0)[i] = v;
    }
}

// ---------------------------------------------------------------------------
// Gather-aggregate with 4-way MLP unrolling.
// ---------------------------------------------------------------------------
template<int DIM, bool RELU, bool HASB>
__global__ void agg_kernel(const float* __restrict__ hin,
                           float* __restrict__ hout,
                           const float* __restrict__ bias, int n) {
    constexpr int LPN = (DIM >= 32) ? 32 : DIM;
    constexpr int NPW = 32 / LPN;
    int warp = (blockIdx.x * blockDim.x + threadIdx.x) >> 5;
    int lane = threadIdx.x & 31;
    int node = warp * NPW + (lane / LPN);
    int l = lane % LPN;
    if (node >= n) return;
    int beg = g_row_ptr[node];
    int end = g_row_ptr[node + 1];
    float ni = g_norm_in[node];
    if (DIM == 64) {
        const float* base = hin + l * 2;
        float2 a0 = {0, 0}, a1 = {0, 0}, a2 = {0, 0}, a3 = {0, 0};
        int e = beg;
        for (; e + 3 < end; e += 4) {
            int s0 = g_csr_src[e],     s1 = g_csr_src[e + 1];
            int s2 = g_csr_src[e + 2], s3 = g_csr_src[e + 3];
            float2 v0 = *(const float2*)(base + s0 * 64);
            float2 v1 = *(const float2*)(base + s1 * 64);
            float2 v2 = *(const float2*)(base + s2 * 64);
            float2 v3 = *(const float2*)(base + s3 * 64);
            a0.x += v0.x; a0.y += v0.y; a1.x += v1.x; a1.y += v1.y;
            a2.x += v2.x; a2.y += v2.y; a3.x += v3.x; a3.y += v3.y;
        }
        for (; e < end; e++) {
            float2 v = *(const float2*)(base + g_csr_src[e] * 64);
            a0.x += v.x; a0.y += v.y;
        }
        float ax = (a0.x + a1.x) + (a2.x + a3.x);
        float ay = (a0.y + a1.y) + (a2.y + a3.y);
        ax *= ni; ay *= ni;
        if (HASB) { ax += bias[l * 2]; ay += bias[l * 2 + 1]; }
        if (RELU) { ax = fmaxf(ax, 0.0f); ay = fmaxf(ay, 0.0f); }
        float2 o; o.x = ax; o.y = ay;
        *(float2*)&hout[node * 64 + l * 2] = o;
    } else {
        const float* base = hin + l;
        float a0 = 0, a1 = 0, a2 = 0, a3 = 0;
        int e = beg;
        for (; e + 3 < end; e += 4) {
            int s0 = g_csr_src[e],     s1 = g_csr_src[e + 1];
            int s2 = g_csr_src[e + 2], s3 = g_csr_src[e + 3];
            a0 += base[s0 * DIM]; a1 += base[s1 * DIM];
            a2 += base[s2 * DIM]; a3 += base[s3 * DIM];
        }
        for (; e < end; e++) a0 += base[g_csr_src[e] * DIM];
        float a = (a0 + a1) + (a2 + a3);
        a *= ni;
        if (HASB) a += bias[l];
        if (RELU) a = fmaxf(a, 0.0f);
        hout[node * DIM + l] = a;
    }
}

// ---------------------------------------------------------------------------
// GEMM: out[N,M] = op(in[N,K] @ W[K,M]); 4 cols x 8 rows per thread, f32x2.
// W staged in smem as float4 over 4 consecutive k's, laid out so a warp's
// 32 lanes read consecutive float4s (conflict-free). Input rows broadcast.
// ---------------------------------------------------------------------------
template<int K, int M, bool RELU, bool BIAS, bool RSCALE>
__global__ void __launch_bounds__(256, 2)
gemm_kernel(const float* __restrict__ in,
            const float* __restrict__ W,
            const float* __restrict__ bias,
            const float* __restrict__ rowscale,
            float* __restrict__ out, int n) {
    constexpr int THREADS = 256;
    constexpr int CPT = 4, RPT = 8, NRP = RPT / 2;
    constexpr int CG = M / CPT;
    constexpr int RG = THREADS / CG;
    constexpr int RTILE = RG * RPT;

    extern __shared__ float smem_ext[];
    float4* sWv = (float4*)smem_ext;           // [(K/4)*CPT*CG]
    float*  sIn = smem_ext + (size_t)K * M;    // [RTILE*K]

    // Stage W: sWv[(k4*CPT + c)*CG + cg] = {W[4k4+kk][cg*CPT+c]}
    for (int p = threadIdx.x; p < (K / 4) * M; p += THREADS) {
        int cg = p % CG;
        int c  = (p / CG) % CPT;
        int k4 = p / (CG * CPT);
        int col = cg * CPT + c;
        float4 w;
        w.x = W[(4 * k4 + 0) * M + col];
        w.y = W[(4 * k4 + 1) * M + col];
        w.z = W[(4 * k4 + 2) * M + col];
        w.w = W[(4 * k4 + 3) * M + col];
        sWv[p] = w;
    }

    int cg = threadIdx.x % CG;
    int rg = threadIdx.x / CG;
    int c0 = cg * CPT;
    int r0t = rg * RPT;

    float4 bv = make_float4(0.f, 0.f, 0.f, 0.f);
    if (BIAS) bv = *(const float4*)&bias[c0];

    int ntiles = (n + RTILE - 1) / RTILE;
    for (int t = blockIdx.x; t < ntiles; t += gridDim.x) {
        int row0 = t * RTILE;
        int rows = min(RTILE, n - row0);
        __syncthreads();
        {
            const float4* gin = (const float4*)&in[(size_t)row0 * K];
            float4* s4 = (float4*)sIn;
            int nv = rows * (K / 4);
            for (int idx = threadIdx.x; idx < nv; idx += THREADS)
                s4[idx] = gin[idx];
        }
        __syncthreads();

        ull acc[CPT][NRP];
        #pragma unroll
        for (int c = 0; c < CPT; c++)
            #pragma unroll
            for (int rp = 0; rp < NRP; rp++) acc[c][rp] = 0ULL;

        #pragma unroll 4
        for (int k4 = 0; k4 < K / 4; k4++) {
            ull w2[CPT][4];
            #pragma unroll
            for (int c = 0; c < CPT; c++) {
                float4 w = sWv[(k4 * CPT + c) * CG + cg];
                w2[c][0] = pk(w.x, w.x); w2[c][1] = pk(w.y, w.y);
                w2[c][2] = pk(w.z, w.z); w2[c][3] = pk(w.w, w.w);
            }
            #pragma unroll
            for (int rp = 0; rp < NRP; rp++) {
                float4 xa = *(const float4*)&sIn[(r0t + 2 * rp) * K + k4 * 4];
                float4 xb = *(const float4*)&sIn[(r0t + 2 * rp + 1) * K + k4 * 4];
                ull x0 = pk(xa.x, xb.x), x1 = pk(xa.y, xb.y);
                ull x2 = pk(xa.z, xb.z), x3 = pk(xa.w, xb.w);
                #pragma unroll
                for (int c = 0; c < CPT; c++) {
                    fma2(acc[c][rp], x0, w2[c][0]);
                    fma2(acc[c][rp], x1, w2[c][1]);
                    fma2(acc[c][rp], x2, w2[c][2]);
                    fma2(acc[c][rp], x3, w2[c][3]);
                }
            }
        }

        #pragma unroll
        for (int rp = 0; rp < NRP; rp++) {
            float2 f0 = upk(acc[0][rp]), f1 = upk(acc[1][rp]);
            float2 f2 = upk(acc[2][rp]), f3 = upk(acc[3][rp]);
            float4 va = make_float4(f0.x, f1.x, f2.x, f3.x);
            float4 vb = make_float4(f0.y, f1.y, f2.y, f3.y);
            int ra = row0 + r0t + 2 * rp, rb = ra + 1;
            if (BIAS) {
                va.x += bv.x; va.y += bv.y; va.z += bv.z; va.w += bv.w;
                vb.x += bv.x; vb.y += bv.y; vb.z += bv.z; vb.w += bv.w;
            }
            if (RSCALE) {
                float sa = rowscale[min(ra, n - 1)], sb = rowscale[min(rb, n - 1)];
                va.x *= sa; va.y *= sa; va.z *= sa; va.w *= sa;
                vb.x *= sb; vb.y *= sb; vb.z *= sb; vb.w *= sb;
            }
            if (RELU) {
                va.x = fmaxf(va.x, 0.f); va.y = fmaxf(va.y, 0.f);
                va.z = fmaxf(va.z, 0.f); va.w = fmaxf(va.w, 0.f);
                vb.x = fmaxf(vb.x, 0.f); vb.y = fmaxf(vb.y, 0.f);
                vb.z = fmaxf(vb.z, 0.f); vb.w = fmaxf(vb.w, 0.f);
            }
            if (r0t + 2 * rp < rows)     *(float4*)&out[(size_t)ra * M + c0] = va;
            if (r0t + 2 * rp + 1 < rows) *(float4*)&out[(size_t)rb * M + c0] = vb;
        }
    }
}

// Final tiny GEMM: K=32, M=4, one row per thread, fused rowscale.
__global__ void gemm4_kernel(const float* __restrict__ in,
                             const float* __restrict__ W,
                             const float* __restrict__ rowscale,
                             float* __restrict__ out, int n) {
    __shared__ float4 sw[32];
    if (threadIdx.x < 32) sw[threadIdx.x] = *(const float4*)&W[threadIdx.x * 4];
    __syncthreads();
    int r = blockIdx.x * blockDim.x + threadIdx.x;
    if (r >= n) return;
    const float* x = in + (size_t)r * 32;
    float4 acc = make_float4(0.f, 0.f, 0.f, 0.f);
    #pragma unroll
    for (int k4 = 0; k4 < 8; k4++) {
        float4 xv = *(const float4*)&x[k4 * 4];
        float4 w0 = sw[k4 * 4], w1 = sw[k4 * 4 + 1], w2 = sw[k4 * 4 + 2], w3 = sw[k4 * 4 + 3];
        acc.x = fmaf(xv.x, w0.x, fmaf(xv.y, w1.x, fmaf(xv.z, w2.x, fmaf(xv.w, w3.x, acc.x))));
        acc.y = fmaf(xv.x, w0.y, fmaf(xv.y, w1.y, fmaf(xv.z, w2.y, fmaf(xv.w, w3.y, acc.y))));
        acc.z = fmaf(xv.x, w0.z, fmaf(xv.y, w1.z, fmaf(xv.z, w2.z, fmaf(xv.w, w3.z, acc.z))));
        acc.w = fmaf(xv.x, w0.w, fmaf(xv.y, w1.w, fmaf(xv.z, w2.w, fmaf(xv.w, w3.w, acc.w))));
    }
    float s = rowscale[r];
    acc.x *= s; acc.y *= s; acc.z *= s; acc.w *= s;
    *(float4*)&out[(size_t)r * 4] = acc;
}

// ---------------------------------------------------------------------------
__global__ void graph_sum_kernel(const float* __restrict__ h,
                                 const int* __restrict__ gid, int n) {
    int i = blockIdx.x * blockDim.x + threadIdx.x;
    unsigned act = __ballot_sync(0xffffffffu, i < n);
    if (i >= n) return;
    int g = gid[i];
    float4 v = *(const float4*)&h[(size_t)i * 4];
    if (act == 0xffffffffu) {
        int g0 = __shfl_sync(0xffffffffu, g, 0);
        if (__all_sync(0xffffffffu, g == g0)) {
            #pragma unroll
            for (int o = 16; o; o >>= 1) {
                v.x += __shfl_xor_sync(0xffffffffu, v.x, o);
                v.y += __shfl_xor_sync(0xffffffffu, v.y, o);
                v.z += __shfl_xor_sync(0xffffffffu, v.z, o);
                v.w += __shfl_xor_sync(0xffffffffu, v.w, o);
            }
            if ((threadIdx.x & 31) == 0) {
                atomicAdd(&g_gsum[g * 4 + 0], v.x);
                atomicAdd(&g_gsum[g * 4 + 1], v.y);
                atomicAdd(&g_gsum[g * 4 + 2], v.z);
                atomicAdd(&g_gsum[g * 4 + 3], v.w);
                atomicAdd(&g_gcnt[g], 32);
            }
            return;
        }
    }
    atomicAdd(&g_gsum[g * 4 + 0], v.x);
    atomicAdd(&g_gsum[g * 4 + 1], v.y);
    atomicAdd(&g_gsum[g * 4 + 2], v.z);
    atomicAdd(&g_gsum[g * 4 + 3], v.w);
    atomicAdd(&g_gcnt[g], 1);
}

__global__ void graph_mean_kernel(float* __restrict__ out, int g) {
    int i = blockIdx.x * blockDim.x + threadIdx.x;
    if (i < g * 4) {
        float c = fmaxf((float)g_gcnt[i >> 2], 1.0f);
        out[i] = g_gsum[i] / c;
    }
}

// ---------------------------------------------------------------------------
extern "C" void kernel_launch(void* const* d_in, const int* in_sizes, int n_in,
                              void* d_out, int out_size) {
    const float* x  = (const float*)d_in[0];
    const float* W1 = (const float*)d_in[1];
    const float* b1 = (const float*)d_in[2];
    const float* W2 = (const float*)d_in[3];
    const float* b2 = (const float*)d_in[4];
    const float* W3 = (const float*)d_in[5];
    const float* b3 = (const float*)d_in[6];
    const float* W4 = (const float*)d_in[7];
    const float* b4 = (const float*)d_in[8];
    const int* src = (const int*)d_in[9];
    const int* dst = (const int*)d_in[10];
    const int* gid = (const int*)d_in[11];
    float* out = (float*)d_out;

    int n = in_sizes[0] / 64;
    int e = in_sizes[9];
    int g = out_size / 4;

    float *h0, *h1, *nrm_out;
    cudaGetSymbolAddress((void**)&h0, g_h0);
    cudaGetSymbolAddress((void**)&h1, g_h1);
    cudaGetSymbolAddress((void**)&nrm_out, g_norm_out);

    const int T = 256;
    auto blocks = [](int work, int t) { return (work + t - 1) / t; };
    auto agg_grid = [&](int npw) {
        int warps = (n + npw - 1) / npw;
        return (warps * 32 + T - 1) / T;
    };

    // Dynamic smem sizes (bytes) per gemm instantiation.
    const int SM1 = (64 * 128 + 64 * 64) * 4;    // 49152
    const int SM2 = (128 * 64 + 128 * 128) * 4;  // 98304
    const int SM3 = (64 * 32 + 256 * 64) * 4;    // 73728
    cudaFuncSetAttribute((const void*)gemm_kernel<64, 128, true, true, false>,
                         cudaFuncAttributeMaxDynamicSharedMemorySize, SM1);
    cudaFuncSetAttribute((const void*)gemm_kernel<128, 64, false, false, true>,
                         cudaFuncAttributeMaxDynamicSharedMemorySize, SM2);
    cudaFuncSetAttribute((const void*)gemm_kernel<64, 32, false, false, true>,
                         cudaFuncAttributeMaxDynamicSharedMemorySize, SM3);

    // Graph preprocessing
    int nb = (n + 1023) / 1024;
    zero_kernel<<<blocks(n, T), T>>>(n, g);
    degree_kernel<<<blocks(e, T), T>>>(src, dst, e);
    norm_kernel<<<blocks(n, T), T>>>(n);
    scan_pass1<<<nb, 256>>>(n);
    scan_pass2<<<1, 128>>>(nb, n);
    scan_pass3<<<nb, 256>>>(n);
    csr_fill_kernel<<<blocks(e, T), T>>>(src, dst, e);

    const int GG = 296;  // 2 blocks per SM

    // Layer 1: agg(x * norm_out) -> (* norm_in) -> @W1 + b1 -> relu
    scale_x_kernel<<<blocks(n * 16, T), T>>>(x, n);
    agg_kernel<64, false, false><<<agg_grid(1), T>>>(h0, h1, nullptr, n);
    gemm_kernel<64, 128, true, true, false><<<GG, 256, SM1>>>(h1, W1, b1, nullptr, h0, n);

    // Layer 2: (h @ W2) * norm_out -> agg -> * norm_in + b2 -> relu
    gemm_kernel<128, 64, false, false, true><<<GG, 256, SM2>>>(h0, W2, nullptr, nrm_out, h1, n);
    agg_kernel<64, true, true><<<agg_grid(1), T>>>(h1, h0, b2, n);

    // Layer 3
    gemm_kernel<64, 32, false, false, true><<<GG, 256, SM3>>>(h0, W3, nullptr, nrm_out, h1, n);
    agg_kernel<32, true, true><<<agg_grid(1), T>>>(h1, h0, b3, n);

    // Layer 4 (no relu)
    gemm4_kernel<<<blocks(n, T), T>>>(h0, W4, nrm_out, h1, n);
    agg_kernel<4, false, true><<<agg_grid(8), T>>>(h1, h0, b4, n);

    // Per-graph mean readout
    graph_sum_kernel<<<blocks(n, T), T>>>(h0, gid, n);
    graph_mean_kernel<<<blocks(g * 4, T), T>>>(out, g);
}